// round 1
// baseline (speedup 1.0000x reference)
#include <cuda_runtime.h>
#include <cstdint>

#define BSZ   8
#define NT    128
#define CH    1024
#define KH    4
#define HDIM  512
#define GDIM  2048
#define NHEAD 8
#define CPH   16      // CTAs per head
#define NCTA  128

// ---------------- static device scratch (no cudaMalloc allowed) ----------------
__device__ float g_xT[KH * NT * BSZ * CH];                 // [k][t][b][c]      16.8 MB
__device__ float g_whhT[NHEAD * HDIM * GDIM];              // [hd][c][g]        33.5 MB
__device__ float g_xproj[NHEAD * NT * GDIM * BSZ];         // [hd][t][g][b]     67 MB
__device__ float g_hbuf[2 * NHEAD * HDIM * BSZ];           // [par][hd][h][b]
__device__ unsigned g_barcnt[NHEAD * 32];
__device__ unsigned g_bargen[NHEAD * 32];

// ---------------- f32x2 helpers ----------------
union F2U { unsigned long long u; float2 f; };

__device__ __forceinline__ unsigned long long pk2(float a, float b) {
    unsigned long long r;
    asm("mov.b64 %0, {%1,%2};" : "=l"(r) : "f"(a), "f"(b));
    return r;
}
__device__ __forceinline__ void fma2(unsigned long long &d,
                                     unsigned long long a,
                                     unsigned long long b) {
    asm("fma.rn.f32x2 %0, %1, %2, %0;" : "+l"(d) : "l"(a), "l"(b));
}

// ---------------- init: zero barriers + h buffers ----------------
__global__ void k_init() {
    int idx = blockIdx.x * blockDim.x + threadIdx.x;
    if (idx < NHEAD) { g_barcnt[idx * 32] = 0u; g_bargen[idx * 32] = 0u; }
    if (idx < 2 * NHEAD * HDIM * BSZ) g_hbuf[idx] = 0.f;
}

// ---------------- transpose x: [b][t][c][k] -> [k][t][b][c] ----------------
__global__ void k_xT(const float* __restrict__ x) {
    int idx = blockIdx.x * blockDim.x + threadIdx.x;   // 4,194,304 total
    int c = idx & (CH - 1);
    int b = (idx >> 10) & 7;
    int t = (idx >> 13) & 127;
    int k = idx >> 20;
    g_xT[idx] = x[((b * NT + t) * CH + c) * KH + k];
}

// ---------------- transpose Whh: [dir][k][g][c] -> [hd][c][g] ----------------
__global__ void k_whhT(const float* __restrict__ Wf, const float* __restrict__ Wb) {
    int idx = blockIdx.x * blockDim.x + threadIdx.x;   // 8,388,608 total
    int g = idx & (GDIM - 1);
    int c = (idx >> 11) & (HDIM - 1);
    int hd = idx >> 20;
    int dir = hd >> 2, k = hd & 3;
    const float* W = dir ? Wb : Wf;
    g_whhT[idx] = W[(k * GDIM + g) * HDIM + c];
}

// ---------------- phase-1 GEMM: xproj = xT @ Wih^T + bias ----------------
// per (hd): C[M=1024 (t,b)][N=2048 (g)] = A[M][1024] * W[N][1024]^T
#define BM 128
#define BN 128
#define BK 16
#define PAD 132

__global__ __launch_bounds__(256) void k_gemm(
    const float* __restrict__ Wih_f, const float* __restrict__ Wih_b,
    const float* __restrict__ bih_f, const float* __restrict__ bhh_f,
    const float* __restrict__ bih_b, const float* __restrict__ bhh_b)
{
    __shared__ float As[BK * PAD];
    __shared__ float Bs[BK * PAD];

    const int hd  = blockIdx.z;
    const int dir = hd >> 2, k = hd & 3;
    const float* A  = g_xT + k * (NT * BSZ * CH);
    const float* W  = (dir ? Wih_b : Wih_f) + k * (GDIM * CH);
    const float* bi = (dir ? bih_b : bih_f) + k * GDIM;
    const float* bh = (dir ? bhh_b : bhh_f) + k * GDIM;

    const int m0blk = blockIdx.y * BM;
    const int n0blk = blockIdx.x * BN;
    const int tid = threadIdx.x;
    const int tx = tid & 15, ty = tid >> 4;

    unsigned long long acc[4][8];
    #pragma unroll
    for (int i = 0; i < 4; i++)
        #pragma unroll
        for (int j = 0; j < 8; j++) acc[i][j] = 0ull;

    #pragma unroll 1
    for (int c0 = 0; c0 < CH; c0 += BK) {
        #pragma unroll
        for (int l = 0; l < 2; l++) {
            int li = tid + l * 256;
            int m  = li >> 2, c4 = li & 3;
            float4 va = *(const float4*)&A[(m0blk + m) * CH + c0 + c4 * 4];
            As[(c4 * 4 + 0) * PAD + m] = va.x;
            As[(c4 * 4 + 1) * PAD + m] = va.y;
            As[(c4 * 4 + 2) * PAD + m] = va.z;
            As[(c4 * 4 + 3) * PAD + m] = va.w;
            float4 vb = *(const float4*)&W[(n0blk + m) * CH + c0 + c4 * 4];
            Bs[(c4 * 4 + 0) * PAD + m] = vb.x;
            Bs[(c4 * 4 + 1) * PAD + m] = vb.y;
            Bs[(c4 * 4 + 2) * PAD + m] = vb.z;
            Bs[(c4 * 4 + 3) * PAD + m] = vb.w;
        }
        __syncthreads();

        #pragma unroll
        for (int c = 0; c < BK; c++) {
            const float4* ap = (const float4*)&As[c * PAD + ty * 8];
            float4 a0 = ap[0], a1 = ap[1];
            const float4* bp = (const float4*)&Bs[c * PAD + tx * 8];
            float4 b0 = bp[0], b1 = bp[1];
            unsigned long long am[4];
            am[0] = pk2(a0.x, a0.y); am[1] = pk2(a0.z, a0.w);
            am[2] = pk2(a1.x, a1.y); am[3] = pk2(a1.z, a1.w);
            float bv[8] = {b0.x, b0.y, b0.z, b0.w, b1.x, b1.y, b1.z, b1.w};
            #pragma unroll
            for (int j = 0; j < 8; j++) {
                unsigned long long bd = pk2(bv[j], bv[j]);
                fma2(acc[0][j], am[0], bd);
                fma2(acc[1][j], am[1], bd);
                fma2(acc[2][j], am[2], bd);
                fma2(acc[3][j], am[3], bd);
            }
        }
        __syncthreads();
    }

    // epilogue: m rows of this thread are one t, b = 0..7 ; write [hd][t][g][b]
    const int t = (m0blk + ty * 8) >> 3;
    #pragma unroll
    for (int j = 0; j < 8; j++) {
        int g = n0blk + tx * 8 + j;
        float bias = bi[g] + bh[g];
        float* op = &g_xproj[((hd * NT + t) * GDIM + g) * BSZ];
        #pragma unroll
        for (int i = 0; i < 4; i++) {
            F2U u; u.u = acc[i][j];
            op[2 * i]     = u.f.x + bias;
            op[2 * i + 1] = u.f.y + bias;
        }
    }
}

// ---------------- phase-2: persistent recurrent scan ----------------
// 128 CTAs (16 per head), 256 threads. Per CTA: 32 h values (128 gate rows).
// GEMM role: cg = warp (c-chunk of 64), rg = lane (4 consecutive g rows).
// Finalize role: thread = (hh 0..31, b 0..7); c-state in registers.
__global__ __launch_bounds__(256) void k_lstm(float* __restrict__ out) {
    __shared__ float smem[8480];   // union: shh[4096] during GEMM, spf afterwards
    float* shh = smem;
    float* spf = smem;

    const int cta = blockIdx.x;
    const int hd  = cta >> 4;
    const int ci  = cta & 15;
    const int h0  = ci * 32;
    const int dir = hd >> 2;
    const int k   = hd & 3;
    const int tid = threadIdx.x;
    const int cg  = tid >> 5, rg = tid & 31;
    const int g0  = (rg >> 3) * HDIM + h0 + (rg & 7) * 4;
    const float* wbase = g_whhT + (size_t)hd * HDIM * GDIM + g0;
    const int cbeg = cg * 64;

    const int fhh = tid >> 3, fb = tid & 7;
    const int rgi_base = fhh >> 2;
    const int ii = fhh & 3;
    const int bp = fb >> 1;
    const int lodd = fb & 1;
    float c_state = 0.f;

    unsigned* bcnt = &g_barcnt[hd * 32];
    volatile unsigned* bgen = &g_bargen[hd * 32];

    for (int s = 0; s < NT; s++) {
        const int par = s & 1;
        // load h_prev [c][b] into smem (L2-coherent loads)
        {
            const float4* src = (const float4*)(g_hbuf + (size_t)(par * NHEAD + hd) * HDIM * BSZ);
            float4* dst = (float4*)shh;
            #pragma unroll
            for (int l = 0; l < 4; l++) dst[tid + l * 256] = __ldcg(&src[tid + l * 256]);
        }
        __syncthreads();

        unsigned long long acc[4][4];
        #pragma unroll
        for (int i = 0; i < 4; i++)
            #pragma unroll
            for (int j = 0; j < 4; j++) acc[i][j] = 0ull;

        #pragma unroll 4
        for (int c = cbeg; c < cbeg + 64; c++) {
            float4 w = __ldg((const float4*)(wbase + (size_t)c * GDIM));
            const float4* hp = (const float4*)(shh + c * 8);
            float4 h03 = hp[0], h47 = hp[1];
            unsigned long long hb0 = pk2(h03.x, h03.y);
            unsigned long long hb1 = pk2(h03.z, h03.w);
            unsigned long long hb2 = pk2(h47.x, h47.y);
            unsigned long long hb3 = pk2(h47.z, h47.w);
            unsigned long long w2;
            w2 = pk2(w.x, w.x);
            fma2(acc[0][0], w2, hb0); fma2(acc[0][1], w2, hb1);
            fma2(acc[0][2], w2, hb2); fma2(acc[0][3], w2, hb3);
            w2 = pk2(w.y, w.y);
            fma2(acc[1][0], w2, hb0); fma2(acc[1][1], w2, hb1);
            fma2(acc[1][2], w2, hb2); fma2(acc[1][3], w2, hb3);
            w2 = pk2(w.z, w.z);
            fma2(acc[2][0], w2, hb0); fma2(acc[2][1], w2, hb1);
            fma2(acc[2][2], w2, hb2); fma2(acc[2][3], w2, hb3);
            w2 = pk2(w.w, w.w);
            fma2(acc[3][0], w2, hb0); fma2(acc[3][1], w2, hb1);
            fma2(acc[3][2], w2, hb2); fma2(acc[3][3], w2, hb3);
        }
        __syncthreads();   // all shh reads done; smem reused as spf

        // store partials: spf[af][cg][rg] with af-stride 265 (bank-conflict-free)
        #pragma unroll
        for (int i = 0; i < 4; i++)
            #pragma unroll
            for (int j = 0; j < 4; j++) {
                F2U u; u.u = acc[i][j];
                int af = (i * 4 + j) * 2;
                spf[af * 265 + cg * 33 + rg]       = u.f.x;
                spf[(af + 1) * 265 + cg * 33 + rg] = u.f.y;
            }
        __syncthreads();

        // finalize: thread (fhh, fb)
        const int t = dir ? (NT - 1 - s) : s;
        float pre[4];
        #pragma unroll
        for (int gate = 0; gate < 4; gate++) {
            const int af  = (ii * 4 + bp) * 2 + lodd;
            const int rgi = gate * 8 + rgi_base;
            float ssum = 0.f;
            #pragma unroll
            for (int c8 = 0; c8 < 8; c8++)
                ssum += spf[af * 265 + c8 * 33 + rgi];
            const int g = gate * HDIM + h0 + fhh;
            pre[gate] = ssum + __ldg(&g_xproj[(((size_t)hd * NT + t) * GDIM + g) * BSZ + fb]);
        }
        float ig = 1.f / (1.f + expf(-pre[0]));
        float fg = 1.f / (1.f + expf(-pre[1]));
        float gt = tanhf(pre[2]);
        float og = 1.f / (1.f + expf(-pre[3]));
        c_state = fg * c_state + ig * gt;
        float hnew = og * tanhf(c_state);

        g_hbuf[(size_t)((par ^ 1) * NHEAD + hd) * HDIM * BSZ + (h0 + fhh) * BSZ + fb] = hnew;
        out[(((size_t)fb * NT + t) * (2 * HDIM) + dir * HDIM + h0 + fhh) * KH + k] = hnew;

        // per-head grid barrier (16 CTAs), monotone counter
        if (s < NT - 1) {
            __threadfence();
            __syncthreads();
            if (tid == 0) {
                unsigned a = atomicAdd(bcnt, 1u);
                if (a == (unsigned)(s * CPH + CPH - 1)) {
                    atomicExch((unsigned*)bgen, (unsigned)(s + 1));
                } else {
                    while (*bgen <= (unsigned)s) __nanosleep(64);
                }
            }
            __syncthreads();
        }
    }
}

// ---------------- launch ----------------
extern "C" void kernel_launch(void* const* d_in, const int* in_sizes, int n_in,
                              void* d_out, int out_size) {
    const float* x     = (const float*)d_in[0];
    const float* Wih_f = (const float*)d_in[1];
    const float* Whh_f = (const float*)d_in[2];
    const float* bih_f = (const float*)d_in[3];
    const float* bhh_f = (const float*)d_in[4];
    const float* Wih_b = (const float*)d_in[5];
    const float* Whh_b = (const float*)d_in[6];
    const float* bih_b = (const float*)d_in[7];
    const float* bhh_b = (const float*)d_in[8];
    float* out = (float*)d_out;

    k_init<<<256, 256>>>();
    k_xT<<<(KH * NT * BSZ * CH) / 256, 256>>>(x);
    k_whhT<<<(NHEAD * HDIM * GDIM) / 256, 256>>>(Whh_f, Whh_b);
    dim3 gg(GDIM / BN, (NT * BSZ) / BM, NHEAD);
    k_gemm<<<gg, 256>>>(Wih_f, Wih_b, bih_f, bhh_f, bih_b, bhh_b);
    k_lstm<<<NCTA, 256>>>(out);
}

// round 6
// speedup vs baseline: 1.2862x; 1.2862x over previous
#include <cuda_runtime.h>
#include <cstdint>

#define BSZ   8
#define NT    128
#define CH    1024
#define KH    4
#define HDIM  512
#define GDIM  2048
#define NHEAD 8
#define CPH   16
#define NCTA  128

#define SPF_STRIDE 529                 // >= 16*33+31+1, and odd mod 32 (17) => conflict-free finalize
#define LSTM_SMEM_FLOATS (32 * SPF_STRIDE)   // 16928 floats = 67712 B

// ---------------- static device scratch ----------------
__device__ float g_xT[KH * NT * BSZ * CH];                 // [k][t][b][c]
__device__ float g_whhT[NHEAD * HDIM * GDIM];              // [hd][c][g]
__device__ float g_xproj[NHEAD * NT * GDIM * BSZ];         // [hd][t][g][b]
__device__ float g_hbuf[2 * NHEAD * HDIM * BSZ];           // [par][hd][h][b]
__device__ unsigned g_flag[NHEAD * CPH];                   // per-CTA step flags

// ---------------- helpers ----------------
union F2U { unsigned long long u; float2 f; };

__device__ __forceinline__ unsigned long long pk2(float a, float b) {
    unsigned long long r;
    asm("mov.b64 %0, {%1,%2};" : "=l"(r) : "f"(a), "f"(b));
    return r;
}
__device__ __forceinline__ void fma2(unsigned long long &d,
                                     unsigned long long a,
                                     unsigned long long b) {
    asm("fma.rn.f32x2 %0, %1, %2, %0;" : "+l"(d) : "l"(a), "l"(b));
}
__device__ __forceinline__ uint32_t f2tf(float f) {
    uint32_t u; asm("cvt.rna.tf32.f32 %0, %1;" : "=r"(u) : "f"(f)); return u;
}
__device__ __forceinline__ void mma_tf32(float* d, const uint32_t* a, const uint32_t* b) {
    asm volatile("mma.sync.aligned.m16n8k8.row.col.f32.tf32.tf32.f32 "
        "{%0,%1,%2,%3}, {%4,%5,%6,%7}, {%8,%9}, {%0,%1,%2,%3};"
        : "+f"(d[0]), "+f"(d[1]), "+f"(d[2]), "+f"(d[3])
        : "r"(a[0]), "r"(a[1]), "r"(a[2]), "r"(a[3]), "r"(b[0]), "r"(b[1]));
}

// ---------------- init ----------------
__global__ void k_init() {
    int idx = blockIdx.x * blockDim.x + threadIdx.x;
    if (idx < NHEAD * CPH) g_flag[idx] = 0u;
    if (idx < 2 * NHEAD * HDIM * BSZ) g_hbuf[idx] = 0.f;
}

// ---------------- transpose x: [b][t][c][k] -> [k][t][b][c] ----------------
__global__ void k_xT(const float* __restrict__ x) {
    int c = blockIdx.x * 128 + threadIdx.x;
    int t = blockIdx.y, b = blockIdx.z;
    float4 v = *(const float4*)&x[(size_t)((b * NT + t) * CH + c) * KH];
    const size_t plane = (size_t)NT * BSZ * CH;
    const size_t o = (size_t)(t * BSZ + b) * CH + c;
    g_xT[o]             = v.x;
    g_xT[o + plane]     = v.y;
    g_xT[o + 2 * plane] = v.z;
    g_xT[o + 3 * plane] = v.w;
}

// ---------------- tiled transpose Whh: [dir][k][g][c] -> [hd][c][g] ----------------
__global__ void k_whhT(const float* __restrict__ Wf, const float* __restrict__ Wb) {
    __shared__ float tile[32][33];
    const int hd = blockIdx.z;
    const int dir = hd >> 2, k = hd & 3;
    const float* W = (dir ? Wb : Wf) + (size_t)k * GDIM * HDIM;
    const int g0 = blockIdx.x * 32;
    const int c0 = blockIdx.y * 32;
    const int tx = threadIdx.x & 31, ty = threadIdx.x >> 5;   // 32x8
    #pragma unroll
    for (int i = 0; i < 4; i++)
        tile[ty + 8 * i][tx] = W[(size_t)(g0 + ty + 8 * i) * HDIM + c0 + tx];
    __syncthreads();
    float* O = g_whhT + (size_t)hd * HDIM * GDIM;
    #pragma unroll
    for (int i = 0; i < 4; i++)
        O[(size_t)(c0 + ty + 8 * i) * GDIM + g0 + tx] = tile[tx][ty + 8 * i];
}

// ---------------- phase-1 GEMM via tf32 mma.sync ----------------
// per head: C[M=1024][N=2048] = A[M][1024] * W[N][1024]^T   (both K-contiguous)
// CTA tile 128x128, 8 warps in 2(M) x 4(N), warp tile 64x32, BK=32.
#define ALD 36

__global__ __launch_bounds__(256) void k_gemm(
    const float* __restrict__ Wih_f, const float* __restrict__ Wih_b,
    const float* __restrict__ bih_f, const float* __restrict__ bhh_f,
    const float* __restrict__ bih_b, const float* __restrict__ bhh_b)
{
    __shared__ uint32_t As[128 * ALD];
    __shared__ uint32_t Bs[128 * ALD];

    const int hd = blockIdx.z, dir = hd >> 2, k = hd & 3;
    const float* A = g_xT + (size_t)k * (NT * BSZ * CH) + (size_t)blockIdx.y * 128 * CH;
    const float* W = (dir ? Wih_b : Wih_f) + (size_t)k * GDIM * CH + (size_t)blockIdx.x * 128 * CH;
    const float* bi = (dir ? bih_b : bih_f) + k * GDIM;
    const float* bh = (dir ? bhh_b : bhh_f) + k * GDIM;

    const int tid = threadIdx.x, lane = tid & 31, wid = tid >> 5;
    const int wm = (wid & 1) * 64, wn = (wid >> 1) * 32;
    const int grp = lane >> 2, tig = lane & 3;

    float acc[4][4][4];
    #pragma unroll
    for (int a = 0; a < 4; a++)
        #pragma unroll
        for (int b = 0; b < 4; b++)
            #pragma unroll
            for (int c = 0; c < 4; c++) acc[a][b][c] = 0.f;

    const int lr = tid >> 3;            // 0..31
    const int lcf = (tid & 7) * 4;      // 0,4,...,28
    const int kb = lcf >> 3, lo = (lcf >> 2) & 1;
    const int sbase = kb * 8 + lo;

    float4 pa[4], pb[4];
    #pragma unroll
    for (int i = 0; i < 4; i++) {
        pa[i] = *(const float4*)&A[(size_t)(lr + 32 * i) * CH + lcf];
        pb[i] = *(const float4*)&W[(size_t)(lr + 32 * i) * CH + lcf];
    }

    for (int c0 = 0; c0 < CH; c0 += 32) {
        if (c0) __syncthreads();
        #pragma unroll
        for (int i = 0; i < 4; i++) {
            int r = lr + 32 * i;
            As[r * ALD + sbase + 0] = f2tf(pa[i].x);
            As[r * ALD + sbase + 2] = f2tf(pa[i].y);
            As[r * ALD + sbase + 4] = f2tf(pa[i].z);
            As[r * ALD + sbase + 6] = f2tf(pa[i].w);
            Bs[r * ALD + sbase + 0] = f2tf(pb[i].x);
            Bs[r * ALD + sbase + 2] = f2tf(pb[i].y);
            Bs[r * ALD + sbase + 4] = f2tf(pb[i].z);
            Bs[r * ALD + sbase + 6] = f2tf(pb[i].w);
        }
        __syncthreads();
        if (c0 + 32 < CH) {
            #pragma unroll
            for (int i = 0; i < 4; i++) {
                pa[i] = *(const float4*)&A[(size_t)(lr + 32 * i) * CH + c0 + 32 + lcf];
                pb[i] = *(const float4*)&W[(size_t)(lr + 32 * i) * CH + c0 + 32 + lcf];
            }
        }
        #pragma unroll
        for (int kk = 0; kk < 4; kk++) {
            uint32_t af[4][4], bf[4][2];
            #pragma unroll
            for (int mt = 0; mt < 4; mt++) {
                int r = wm + mt * 16 + grp;
                uint2 v0 = *(const uint2*)&As[r * ALD + kk * 8 + 2 * tig];
                uint2 v1 = *(const uint2*)&As[(r + 8) * ALD + kk * 8 + 2 * tig];
                af[mt][0] = v0.x; af[mt][1] = v1.x; af[mt][2] = v0.y; af[mt][3] = v1.y;
            }
            #pragma unroll
            for (int nt = 0; nt < 4; nt++) {
                int r = wn + nt * 8 + grp;
                uint2 v = *(const uint2*)&Bs[r * ALD + kk * 8 + 2 * tig];
                bf[nt][0] = v.x; bf[nt][1] = v.y;
            }
            #pragma unroll
            for (int mt = 0; mt < 4; mt++)
                #pragma unroll
                for (int nt = 0; nt < 4; nt++)
                    mma_tf32(acc[mt][nt], af[mt], bf[nt]);
        }
    }

    // epilogue with bias; write [hd][t][g][b]
    const int gm0 = blockIdx.y * 128 + wm;
    const int gn0 = blockIdx.x * 128 + wn;
    #pragma unroll
    for (int nt = 0; nt < 4; nt++) {
        int g = gn0 + nt * 8 + 2 * tig;
        float b0 = bi[g] + bh[g];
        float b1 = bi[g + 1] + bh[g + 1];
        #pragma unroll
        for (int mt = 0; mt < 4; mt++) {
            int m = gm0 + mt * 16 + grp;
            {
                int t = m >> 3, b = m & 7;
                float* o = &g_xproj[(((size_t)hd * NT + t) * GDIM + g) * BSZ + b];
                o[0]   = acc[mt][nt][0] + b0;
                o[BSZ] = acc[mt][nt][1] + b1;
            }
            {
                int m2 = m + 8;
                int t = m2 >> 3, b = m2 & 7;
                float* o = &g_xproj[(((size_t)hd * NT + t) * GDIM + g) * BSZ + b];
                o[0]   = acc[mt][nt][2] + b0;
                o[BSZ] = acc[mt][nt][3] + b1;
            }
        }
    }
}

// ---------------- phase-2: persistent recurrent scan ----------------
// 128 CTAs (16/head), 512 threads (16 warps). CTA owns 32 h (128 gate rows).
// Partials: spf[af][cg][rg], af-stride SPF_STRIDE (529) — no aliasing, odd mod 32.
__global__ __launch_bounds__(512) void k_lstm(float* __restrict__ out) {
    extern __shared__ float smem[];
    float* shh = smem;
    float* spf = smem;

    const int cta = blockIdx.x;
    const int hd  = cta >> 4;
    const int ci  = cta & 15;
    const int h0  = ci * 32;
    const int dir = hd >> 2;
    const int k   = hd & 3;
    const int tid = threadIdx.x;
    const int cg  = tid >> 5, rg = tid & 31;
    const int g0  = (rg >> 3) * HDIM + h0 + (rg & 7) * 4;
    const float* wbase = g_whhT + (size_t)hd * HDIM * GDIM + g0;
    const int cbeg = cg * 32;

    const int fhh = tid >> 3, fb = tid & 7;  // finalize role, valid for tid<256
    const int rgi_base = fhh >> 2;
    const int ii = fhh & 3;
    const int af_fin = ii * 8 + fb;          // == (ii*4 + (fb>>1))*2 + (fb&1)
    float c_state = 0.f;

    volatile unsigned* flg = g_flag + hd * CPH;

    for (int s = 0; s < NT; s++) {
        const int par = s & 1;
        const int t = dir ? (NT - 1 - s) : s;

        // prefetch xproj for this step (independent of h)
        float xp0 = 0.f, xp1 = 0.f, xp2 = 0.f, xp3 = 0.f;
        if (tid < 256) {
            const float* xb = &g_xproj[(((size_t)hd * NT + t) * GDIM + h0 + fhh) * BSZ + fb];
            xp0 = __ldg(xb);
            xp1 = __ldg(xb + (size_t)1 * HDIM * BSZ);
            xp2 = __ldg(xb + (size_t)2 * HDIM * BSZ);
            xp3 = __ldg(xb + (size_t)3 * HDIM * BSZ);
        }

        // load h_prev [c][b] into smem
        {
            const float4* src = (const float4*)(g_hbuf + (size_t)(par * NHEAD + hd) * HDIM * BSZ);
            float4* dst = (float4*)shh;
            dst[tid]       = __ldcg(&src[tid]);
            dst[tid + 512] = __ldcg(&src[tid + 512]);
        }
        __syncthreads();

        unsigned long long acc[4][4];
        #pragma unroll
        for (int i = 0; i < 4; i++)
            #pragma unroll
            for (int j = 0; j < 4; j++) acc[i][j] = 0ull;

        #pragma unroll 8
        for (int c = cbeg; c < cbeg + 32; c++) {
            float4 w = __ldg((const float4*)(wbase + (size_t)c * GDIM));
            const float4* hp = (const float4*)(shh + c * 8);
            float4 h03 = hp[0], h47 = hp[1];
            unsigned long long hb0 = pk2(h03.x, h03.y);
            unsigned long long hb1 = pk2(h03.z, h03.w);
            unsigned long long hb2 = pk2(h47.x, h47.y);
            unsigned long long hb3 = pk2(h47.z, h47.w);
            unsigned long long w2;
            w2 = pk2(w.x, w.x);
            fma2(acc[0][0], w2, hb0); fma2(acc[0][1], w2, hb1);
            fma2(acc[0][2], w2, hb2); fma2(acc[0][3], w2, hb3);
            w2 = pk2(w.y, w.y);
            fma2(acc[1][0], w2, hb0); fma2(acc[1][1], w2, hb1);
            fma2(acc[1][2], w2, hb2); fma2(acc[1][3], w2, hb3);
            w2 = pk2(w.z, w.z);
            fma2(acc[2][0], w2, hb0); fma2(acc[2][1], w2, hb1);
            fma2(acc[2][2], w2, hb2); fma2(acc[2][3], w2, hb3);
            w2 = pk2(w.w, w.w);
            fma2(acc[3][0], w2, hb0); fma2(acc[3][1], w2, hb1);
            fma2(acc[3][2], w2, hb2); fma2(acc[3][3], w2, hb3);
        }
        __syncthreads();   // all shh reads done; smem reused as spf

        #pragma unroll
        for (int i = 0; i < 4; i++)
            #pragma unroll
            for (int j = 0; j < 4; j++) {
                F2U u; u.u = acc[i][j];
                int af = (i * 4 + j) * 2;
                spf[af * SPF_STRIDE + cg * 33 + rg]       = u.f.x;
                spf[(af + 1) * SPF_STRIDE + cg * 33 + rg] = u.f.y;
            }
        __syncthreads();

        if (tid < 256) {
            float pre0 = xp0, pre1 = xp1, pre2 = xp2, pre3 = xp3;
            #pragma unroll
            for (int c8 = 0; c8 < 16; c8++) {
                const float* base = &spf[af_fin * SPF_STRIDE + c8 * 33];
                pre0 += base[0 * 8 + rgi_base];
                pre1 += base[1 * 8 + rgi_base];
                pre2 += base[2 * 8 + rgi_base];
                pre3 += base[3 * 8 + rgi_base];
            }
            float ig = 1.f / (1.f + expf(-pre0));
            float fg = 1.f / (1.f + expf(-pre1));
            float gt = tanhf(pre2);
            float og = 1.f / (1.f + expf(-pre3));
            c_state = fg * c_state + ig * gt;
            float hnew = og * tanhf(c_state);

            g_hbuf[(size_t)((par ^ 1) * NHEAD + hd) * HDIM * BSZ + (h0 + fhh) * BSZ + fb] = hnew;
            out[(((size_t)fb * NT + t) * (2 * HDIM) + dir * HDIM + h0 + fhh) * KH + k] = hnew;
        }

        if (s < NT - 1) {
            __threadfence();
            __syncthreads();
            if (tid == 0)
                *(volatile unsigned*)&g_flag[hd * CPH + ci] = (unsigned)(s + 1);
            if (tid < CPH) {
                while (flg[tid] <= (unsigned)s) { }
            }
            __syncthreads();
        }
    }
}

// ---------------- launch ----------------
extern "C" void kernel_launch(void* const* d_in, const int* in_sizes, int n_in,
                              void* d_out, int out_size) {
    const float* x     = (const float*)d_in[0];
    const float* Wih_f = (const float*)d_in[1];
    const float* Whh_f = (const float*)d_in[2];
    const float* bih_f = (const float*)d_in[3];
    const float* bhh_f = (const float*)d_in[4];
    const float* Wih_b = (const float*)d_in[5];
    const float* Whh_b = (const float*)d_in[6];
    const float* bih_b = (const float*)d_in[7];
    const float* bhh_b = (const float*)d_in[8];
    float* out = (float*)d_out;

    static int smem_set = 0;
    if (!smem_set) {
        cudaFuncSetAttribute(k_lstm, cudaFuncAttributeMaxDynamicSharedMemorySize,
                             LSTM_SMEM_FLOATS * sizeof(float));
        smem_set = 1;
    }

    k_init<<<256, 256>>>();
    dim3 gx(CH / 128, NT, BSZ);
    k_xT<<<gx, 128>>>(x);
    dim3 gw(GDIM / 32, HDIM / 32, NHEAD);
    k_whhT<<<gw, 256>>>(Whh_f, Whh_b);
    dim3 gg(GDIM / 128, (NT * BSZ) / 128, NHEAD);
    k_gemm<<<gg, 256>>>(Wih_f, Wih_b, bih_f, bhh_f, bih_b, bhh_b);
    k_lstm<<<NCTA, 512, LSTM_SMEM_FLOATS * sizeof(float)>>>(out);
}

// round 7
// speedup vs baseline: 1.6236x; 1.2623x over previous
#include <cuda_runtime.h>
#include <cuda_bf16.h>
#include <cstdint>

#define BSZ   8
#define NT    128
#define CH    1024
#define KH    4
#define HDIM  512
#define GDIM  2048
#define NHEAD 8
#define CPH   16
#define NCTA  128

// ---- smem layout for k_lstm (bytes) ----
#define WLO_BYTES   131072                 // 8 warps * 32 kc * 32 lanes * 16B
#define HT_STRIDE32 260                    // u32 row stride for hT: 520 halves (banks 4*g+t, conflict-free)
#define HTHI_OFF    131072
#define HTLO_OFF    (HTHI_OFF + 8320)      // 8 rows * 260 u32 * 4B = 8320
#define PG_OFF      (HTLO_OFF + 8320)      // 147712
#define PG_LD       9                      // padded row (floats)
#define LSTM_SMEM   (PG_OFF + 128 * PG_LD * 4)   // 152320 B

// ---------------- static device scratch ----------------
__device__ float g_xT[KH * NT * BSZ * CH];                 // [k][t][b][c]
__device__ float g_xproj[NHEAD * NT * BSZ * GDIM];         // [hd][t][b][g]
__device__ float g_hbuf[2 * NHEAD * BSZ * HDIM];           // [par][hd][b][h]
__device__ uint4 g_whi[NHEAD * 16 * 8192];                 // frag-order bf16 hi (16.8 MB)
__device__ uint4 g_wlo[NHEAD * 16 * 8192];                 // frag-order bf16 lo
__device__ unsigned g_flag[NHEAD * CPH];

// ---------------- helpers ----------------
__device__ __forceinline__ uint32_t f2tf(float f) {
    uint32_t u; asm("cvt.rna.tf32.f32 %0, %1;" : "=r"(u) : "f"(f)); return u;
}
__device__ __forceinline__ void mma_tf32(float* d, const uint32_t* a, const uint32_t* b) {
    asm volatile("mma.sync.aligned.m16n8k8.row.col.f32.tf32.tf32.f32 "
        "{%0,%1,%2,%3}, {%4,%5,%6,%7}, {%8,%9}, {%0,%1,%2,%3};"
        : "+f"(d[0]), "+f"(d[1]), "+f"(d[2]), "+f"(d[3])
        : "r"(a[0]), "r"(a[1]), "r"(a[2]), "r"(a[3]), "r"(b[0]), "r"(b[1]));
}
__device__ __forceinline__ void mma_bf(float* d, uint4 a, unsigned b0, unsigned b1) {
    asm volatile("mma.sync.aligned.m16n8k16.row.col.f32.bf16.bf16.f32 "
        "{%0,%1,%2,%3},{%4,%5,%6,%7},{%8,%9},{%0,%1,%2,%3};"
        : "+f"(d[0]), "+f"(d[1]), "+f"(d[2]), "+f"(d[3])
        : "r"(a.x), "r"(a.y), "r"(a.z), "r"(a.w), "r"(b0), "r"(b1));
}
// split two floats into packed bf16 hi (returned) and lo (out param); low 16 bits = first arg
__device__ __forceinline__ unsigned bfsplit2(float x, float y, unsigned &lo) {
    __nv_bfloat16 hx = __float2bfloat16_rn(x), hy = __float2bfloat16_rn(y);
    float rx = x - __bfloat162float(hx), ry = y - __bfloat162float(hy);
    __nv_bfloat16 lx = __float2bfloat16_rn(rx), ly = __float2bfloat16_rn(ry);
    unsigned short uhx = *(unsigned short*)&hx, uhy = *(unsigned short*)&hy;
    unsigned short ulx = *(unsigned short*)&lx, uly = *(unsigned short*)&ly;
    lo = (unsigned)ulx | ((unsigned)uly << 16);
    return (unsigned)uhx | ((unsigned)uhy << 16);
}

// ---------------- init ----------------
__global__ void k_init() {
    int idx = blockIdx.x * blockDim.x + threadIdx.x;
    if (idx < NHEAD * CPH) g_flag[idx] = 0u;
    if (idx < 2 * NHEAD * BSZ * HDIM) g_hbuf[idx] = 0.f;
}

// ---------------- transpose x: [b][t][c][k] -> [k][t][b][c] ----------------
__global__ void k_xT(const float* __restrict__ x) {
    int c = blockIdx.x * 128 + threadIdx.x;
    int t = blockIdx.y, b = blockIdx.z;
    float4 v = *(const float4*)&x[(size_t)((b * NT + t) * CH + c) * KH];
    const size_t plane = (size_t)NT * BSZ * CH;
    const size_t o = (size_t)(t * BSZ + b) * CH + c;
    g_xT[o]             = v.x;
    g_xT[o + plane]     = v.y;
    g_xT[o + 2 * plane] = v.z;
    g_xT[o + 3 * plane] = v.w;
}

// ---------------- Whh -> bf16 hi/lo fragments in mma A-frag order ----------------
// layout: [hd][ci][w][kc][lane] of uint4 {a0,a1,a2,a3}
__global__ void k_wfrag(const float* __restrict__ Wf, const float* __restrict__ Wb) {
    int fi = blockIdx.x * 256 + threadIdx.x;
    int lane = fi & 31, kc = (fi >> 5) & 31, w = (fi >> 10) & 7;
    int ci = (fi >> 13) & 15, hd = fi >> 17;
    int dir = hd >> 2, kk = hd & 3;
    const float* W = (dir ? Wb : Wf) + (size_t)kk * GDIM * HDIM;
    int gID = lane >> 2, t2 = (lane & 3) * 2;
    int r0 = w * 16 + gID, r1 = r0 + 8;
    int gA = (r0 >> 5) * HDIM + ci * 32 + (r0 & 31);
    int gB = (r1 >> 5) * HDIM + ci * 32 + (r1 & 31);
    int c0 = kc * 16 + t2;
    float2 e0 = *(const float2*)&W[(size_t)gA * HDIM + c0];
    float2 e1 = *(const float2*)&W[(size_t)gB * HDIM + c0];
    float2 e2 = *(const float2*)&W[(size_t)gA * HDIM + c0 + 8];
    float2 e3 = *(const float2*)&W[(size_t)gB * HDIM + c0 + 8];
    uint4 hi, lo;
    hi.x = bfsplit2(e0.x, e0.y, lo.x);
    hi.y = bfsplit2(e1.x, e1.y, lo.y);
    hi.z = bfsplit2(e2.x, e2.y, lo.z);
    hi.w = bfsplit2(e3.x, e3.y, lo.w);
    g_whi[fi] = hi;
    g_wlo[fi] = lo;
}

// ---------------- phase-1 GEMM via tf32 mma.sync ----------------
#define ALD 36

__global__ __launch_bounds__(256) void k_gemm(
    const float* __restrict__ Wih_f, const float* __restrict__ Wih_b,
    const float* __restrict__ bih_f, const float* __restrict__ bhh_f,
    const float* __restrict__ bih_b, const float* __restrict__ bhh_b)
{
    __shared__ uint32_t As[128 * ALD];
    __shared__ uint32_t Bs[128 * ALD];

    const int hd = blockIdx.z, dir = hd >> 2, k = hd & 3;
    const float* A = g_xT + (size_t)k * (NT * BSZ * CH) + (size_t)blockIdx.y * 128 * CH;
    const float* W = (dir ? Wih_b : Wih_f) + (size_t)k * GDIM * CH + (size_t)blockIdx.x * 128 * CH;
    const float* bi = (dir ? bih_b : bih_f) + k * GDIM;
    const float* bh = (dir ? bhh_b : bhh_f) + k * GDIM;

    const int tid = threadIdx.x, lane = tid & 31, wid = tid >> 5;
    const int wm = (wid & 1) * 64, wn = (wid >> 1) * 32;
    const int grp = lane >> 2, tig = lane & 3;

    float acc[4][4][4];
    #pragma unroll
    for (int a = 0; a < 4; a++)
        #pragma unroll
        for (int b = 0; b < 4; b++)
            #pragma unroll
            for (int c = 0; c < 4; c++) acc[a][b][c] = 0.f;

    const int lr = tid >> 3;
    const int lcf = (tid & 7) * 4;
    const int kb = lcf >> 3, lo = (lcf >> 2) & 1;
    const int sbase = kb * 8 + lo;

    float4 pa[4], pb[4];
    #pragma unroll
    for (int i = 0; i < 4; i++) {
        pa[i] = *(const float4*)&A[(size_t)(lr + 32 * i) * CH + lcf];
        pb[i] = *(const float4*)&W[(size_t)(lr + 32 * i) * CH + lcf];
    }

    for (int c0 = 0; c0 < CH; c0 += 32) {
        if (c0) __syncthreads();
        #pragma unroll
        for (int i = 0; i < 4; i++) {
            int r = lr + 32 * i;
            As[r * ALD + sbase + 0] = f2tf(pa[i].x);
            As[r * ALD + sbase + 2] = f2tf(pa[i].y);
            As[r * ALD + sbase + 4] = f2tf(pa[i].z);
            As[r * ALD + sbase + 6] = f2tf(pa[i].w);
            Bs[r * ALD + sbase + 0] = f2tf(pb[i].x);
            Bs[r * ALD + sbase + 2] = f2tf(pb[i].y);
            Bs[r * ALD + sbase + 4] = f2tf(pb[i].z);
            Bs[r * ALD + sbase + 6] = f2tf(pb[i].w);
        }
        __syncthreads();
        if (c0 + 32 < CH) {
            #pragma unroll
            for (int i = 0; i < 4; i++) {
                pa[i] = *(const float4*)&A[(size_t)(lr + 32 * i) * CH + c0 + 32 + lcf];
                pb[i] = *(const float4*)&W[(size_t)(lr + 32 * i) * CH + c0 + 32 + lcf];
            }
        }
        #pragma unroll
        for (int kk = 0; kk < 4; kk++) {
            uint32_t af[4][4], bf[4][2];
            #pragma unroll
            for (int mt = 0; mt < 4; mt++) {
                int r = wm + mt * 16 + grp;
                uint2 v0 = *(const uint2*)&As[r * ALD + kk * 8 + 2 * tig];
                uint2 v1 = *(const uint2*)&As[(r + 8) * ALD + kk * 8 + 2 * tig];
                af[mt][0] = v0.x; af[mt][1] = v1.x; af[mt][2] = v0.y; af[mt][3] = v1.y;
            }
            #pragma unroll
            for (int nt = 0; nt < 4; nt++) {
                int r = wn + nt * 8 + grp;
                uint2 v = *(const uint2*)&Bs[r * ALD + kk * 8 + 2 * tig];
                bf[nt][0] = v.x; bf[nt][1] = v.y;
            }
            #pragma unroll
            for (int mt = 0; mt < 4; mt++)
                #pragma unroll
                for (int nt = 0; nt < 4; nt++)
                    mma_tf32(acc[mt][nt], af[mt], bf[nt]);
        }
    }

    // epilogue with bias; write xproj[hd][t][b][g]  (g contiguous -> float2 stores)
    const int gm0 = blockIdx.y * 128 + wm;
    const int gn0 = blockIdx.x * 128 + wn;
    #pragma unroll
    for (int nt = 0; nt < 4; nt++) {
        int g = gn0 + nt * 8 + 2 * tig;
        float b0 = bi[g] + bh[g];
        float b1 = bi[g + 1] + bh[g + 1];
        #pragma unroll
        for (int mt = 0; mt < 4; mt++) {
            int m = gm0 + mt * 16 + grp;
            {
                int t = m >> 3, b = m & 7;
                float2 s; s.x = acc[mt][nt][0] + b0; s.y = acc[mt][nt][1] + b1;
                *(float2*)&g_xproj[(((size_t)hd * NT + t) * BSZ + b) * GDIM + g] = s;
            }
            {
                int m2 = m + 8;
                int t = m2 >> 3, b = m2 & 7;
                float2 s; s.x = acc[mt][nt][2] + b0; s.y = acc[mt][nt][3] + b1;
                *(float2*)&g_xproj[(((size_t)hd * NT + t) * BSZ + b) * GDIM + g] = s;
            }
        }
    }
}

// ---------------- phase-2: persistent recurrent scan (bf16x3 tensor cores) ----------------
// 128 CTAs (16/head), 256 threads (8 warps). CTA owns 32 h (128 gate rows).
// W_hi: resident in registers (A-fragments). W_lo: resident in smem. h: L2 exchange.
__global__ __launch_bounds__(256) void k_lstm(float* __restrict__ out) {
    extern __shared__ char smem[];
    uint4*    wlo_s  = (uint4*)smem;
    unsigned* hthi32 = (unsigned*)(smem + HTHI_OFF);
    unsigned* htlo32 = (unsigned*)(smem + HTLO_OFF);
    float*    pg     = (float*)(smem + PG_OFF);

    const int cta = blockIdx.x;
    const int hd  = cta >> 4;
    const int ci  = cta & 15;
    const int h0  = ci * 32;
    const int dir = hd >> 2;
    const int k   = hd & 3;
    const int tid = threadIdx.x;
    const int wid = tid >> 5, lane = tid & 31;
    const int gID = lane >> 2, t4 = lane & 3;

    // finalize role: warp = one batch, lanes = 32 h values
    const int fb = tid >> 5, fhh = tid & 31;

    // preload W_lo fragments into smem (128 KB, once)
    const uint4* wlo_cta = g_wlo + (size_t)(hd * 16 + ci) * 8192;
    #pragma unroll 4
    for (int i = tid; i < 8192; i += 256) wlo_s[i] = __ldg(&wlo_cta[i]);

    // preload W_hi fragments into registers (128 regs/thread)
    uint4 ahi[32];
    const uint4* whi_cta = g_whi + (size_t)(hd * 16 + ci) * 8192 + wid * 1024 + lane;
    #pragma unroll
    for (int kc = 0; kc < 32; kc++) ahi[kc] = __ldg(&whi_cta[kc * 32]);

    float c_state = 0.f;
    volatile unsigned* flg = g_flag + hd * CPH;

    // prefetch xproj for step 0
    int t = dir ? (NT - 1) : 0;
    float xp[4];
    {
        const float* xb = &g_xproj[(((size_t)hd * NT + t) * BSZ + fb) * GDIM + h0 + fhh];
        #pragma unroll
        for (int g = 0; g < 4; g++) xp[g] = __ldg(xb + g * HDIM);
    }

    for (int s = 0; s < NT; s++) {
        const int par = s & 1;
        t = dir ? (NT - 1 - s) : s;

        // ---- load h (f32, L2) and split to bf16 hi/lo in smem [b][c] padded ----
        {
            const float4* src = (const float4*)(g_hbuf + (size_t)(par * NHEAD + hd) * (BSZ * HDIM));
            const int b = tid >> 5;                 // tid*16 spans one b row
            const int c0 = (tid & 31) * 16;
            unsigned* dhi = hthi32 + b * HT_STRIDE32 + (c0 >> 1);
            unsigned* dlo = htlo32 + b * HT_STRIDE32 + (c0 >> 1);
            #pragma unroll
            for (int j = 0; j < 4; j++) {
                float4 v = __ldcg(&src[tid * 4 + j]);
                unsigned l0, l1;
                unsigned h0w = bfsplit2(v.x, v.y, l0);
                unsigned h1w = bfsplit2(v.z, v.w, l1);
                dhi[j * 2] = h0w; dhi[j * 2 + 1] = h1w;
                dlo[j * 2] = l0;  dlo[j * 2 + 1] = l1;
            }
        }
        __syncthreads();

        // ---- mma: warp owns 16 gate rows x full k=512 ----
        float acc_a[4] = {0.f, 0.f, 0.f, 0.f};
        float acc_b[4] = {0.f, 0.f, 0.f, 0.f};
        {
            const unsigned* bh = hthi32 + gID * HT_STRIDE32;
            const unsigned* bl = htlo32 + gID * HT_STRIDE32;
            const uint4* wl = wlo_s + wid * 1024 + lane;
            #pragma unroll
            for (int kc = 0; kc < 32; kc++) {
                unsigned bh0 = bh[kc * 8 + t4];
                unsigned bh1 = bh[kc * 8 + t4 + 4];
                unsigned bl0 = bl[kc * 8 + t4];
                unsigned bl1 = bl[kc * 8 + t4 + 4];
                uint4 alo = wl[kc * 32];
                mma_bf(acc_a, ahi[kc], bh0, bh1);   // Whi * h_hi
                mma_bf(acc_b, ahi[kc], bl0, bl1);   // Whi * h_lo
                mma_bf(acc_a, alo,     bh0, bh1);   // Wlo * h_hi
            }
        }
        // write pregate partial sums to smem
        {
            int r = wid * 16 + gID;
            int t2 = t4 * 2;
            pg[r * PG_LD + t2]           = acc_a[0] + acc_b[0];
            pg[r * PG_LD + t2 + 1]       = acc_a[1] + acc_b[1];
            pg[(r + 8) * PG_LD + t2]     = acc_a[2] + acc_b[2];
            pg[(r + 8) * PG_LD + t2 + 1] = acc_a[3] + acc_b[3];
        }
        __syncthreads();

        // ---- finalize: thread (fb, fhh) ----
        {
            float pre0 = pg[(0 * 32 + fhh) * PG_LD + fb] + xp[0];
            float pre1 = pg[(1 * 32 + fhh) * PG_LD + fb] + xp[1];
            float pre2 = pg[(2 * 32 + fhh) * PG_LD + fb] + xp[2];
            float pre3 = pg[(3 * 32 + fhh) * PG_LD + fb] + xp[3];
            float ig = 1.f / (1.f + expf(-pre0));
            float fg = 1.f / (1.f + expf(-pre1));
            float gt = tanhf(pre2);
            float og = 1.f / (1.f + expf(-pre3));
            c_state = fg * c_state + ig * gt;
            float hnew = og * tanhf(c_state);

            g_hbuf[(size_t)((par ^ 1) * NHEAD + hd) * (BSZ * HDIM) + fb * HDIM + h0 + fhh] = hnew;
            out[(((size_t)fb * NT + t) * (2 * HDIM) + dir * HDIM + h0 + fhh) * KH + k] = hnew;
        }

        if (s < NT - 1) {
            // prefetch xproj for next step (overlaps barrier)
            int tn = dir ? (NT - 2 - s) : (s + 1);
            {
                const float* xb = &g_xproj[(((size_t)hd * NT + tn) * BSZ + fb) * GDIM + h0 + fhh];
                #pragma unroll
                for (int g = 0; g < 4; g++) xp[g] = __ldg(xb + g * HDIM);
            }
            __threadfence();
            __syncthreads();
            if (tid == 0)
                *(volatile unsigned*)&g_flag[hd * CPH + ci] = (unsigned)(s + 1);
            if (tid < CPH) {
                while (flg[tid] <= (unsigned)s) { }
            }
            __syncthreads();
        }
    }
}

// ---------------- launch ----------------
extern "C" void kernel_launch(void* const* d_in, const int* in_sizes, int n_in,
                              void* d_out, int out_size) {
    const float* x     = (const float*)d_in[0];
    const float* Wih_f = (const float*)d_in[1];
    const float* Whh_f = (const float*)d_in[2];
    const float* bih_f = (const float*)d_in[3];
    const float* bhh_f = (const float*)d_in[4];
    const float* Wih_b = (const float*)d_in[5];
    const float* Whh_b = (const float*)d_in[6];
    const float* bih_b = (const float*)d_in[7];
    const float* bhh_b = (const float*)d_in[8];
    float* out = (float*)d_out;

    static int smem_set = 0;
    if (!smem_set) {
        cudaFuncSetAttribute(k_lstm, cudaFuncAttributeMaxDynamicSharedMemorySize, LSTM_SMEM);
        smem_set = 1;
    }

    k_init<<<256, 256>>>();
    dim3 gx(CH / 128, NT, BSZ);
    k_xT<<<gx, 128>>>(x);
    k_wfrag<<<4096, 256>>>(Whh_f, Whh_b);
    dim3 gg(GDIM / 128, (NT * BSZ) / 128, NHEAD);
    k_gemm<<<gg, 256>>>(Wih_f, Wih_b, bih_f, bhh_f, bih_b, bhh_b);
    k_lstm<<<NCTA, 256, LSTM_SMEM>>>(out);
}